// round 1
// baseline (speedup 1.0000x reference)
#include <cuda_runtime.h>
#include <math.h>

#define Hdim 1024
#define H3   3072
#define Gdim 256
#define Ldim 128
#define NMAX 16384

// ---------------- scratch (device globals; no allocations) ----------------
__device__ float g_msg[NMAX * Hdim];                 // relu(h_atom + bias)
__device__ float g_xg[2][(size_t)NMAX * H3];         // per-atom input-gate projections (f,b)
__device__ float g_h[2][2][Gdim * Hdim];             // [dir][parity] hidden state
__device__ int   g_start[Gdim + 1];                  // segment starts (batch sorted)

// ---------------- meta: segment starts via binary search ----------------
__global__ void k_meta(const int* __restrict__ batch, int n) {
    int g = threadIdx.x;
    if (g > Gdim) return;
    int lo = 0, hi = n;
    while (lo < hi) {
        int mid = (lo + hi) >> 1;
        if (batch[mid] < g) lo = mid + 1; else hi = mid;
    }
    g_start[g] = lo;
}

// ---------------- message = relu(h_atom + bias) ----------------
__global__ void k_message(const float* __restrict__ h_atom,
                          const float* __restrict__ bias, int n4) {
    int i = blockIdx.x * blockDim.x + threadIdx.x;
    if (i >= n4) return;
    float4 v = ((const float4*)h_atom)[i];
    float4 b = ((const float4*)bias)[i & (Hdim / 4 - 1)];
    v.x = fmaxf(v.x + b.x, 0.f);
    v.y = fmaxf(v.y + b.y, 0.f);
    v.z = fmaxf(v.z + b.z, 0.f);
    v.w = fmaxf(v.w + b.w, 0.f);
    ((float4*)g_msg)[i] = v;
}

// ---------------- h0 = segment max of h_atom ----------------
__global__ void k_h0(const float* __restrict__ h_atom) {
    int g = blockIdx.x;
    int c = threadIdx.x * 4;
    int s0 = g_start[g], s1 = g_start[g + 1];
    float4 m = make_float4(-3.4e38f, -3.4e38f, -3.4e38f, -3.4e38f);
    for (int r = s0; r < s1; r++) {
        float4 v = *(const float4*)&h_atom[(size_t)r * Hdim + c];
        m.x = fmaxf(m.x, v.x); m.y = fmaxf(m.y, v.y);
        m.z = fmaxf(m.z, v.z); m.w = fmaxf(m.w, v.w);
    }
    if (s1 == s0) m = make_float4(0.f, 0.f, 0.f, 0.f);
    *(float4*)&g_h[0][0][g * Hdim + c] = m;
    *(float4*)&g_h[1][0][g * Hdim + c] = m;
}

// ---------------- big GEMM: xg[dir] = msg @ w_ih[dir]^T + b_ih[dir] ----------------
// C (n x 3072) = A (n x 1024) * B^T, B = w_ih (3072 x 1024) row-major.
// Tile 128x128, K-tile 16, 256 threads, 8x8 per thread, register prefetch.
__global__ void __launch_bounds__(256) k_gemm_xg(
    const float* __restrict__ w_f, const float* __restrict__ bi_f,
    const float* __restrict__ w_b, const float* __restrict__ bi_b, int n)
{
    int dir = blockIdx.z;
    const float* W  = dir ? w_b : w_f;
    const float* Bv = dir ? bi_b : bi_f;
    float* XG = g_xg[dir];
    int n0 = blockIdx.x * 128;
    int m0 = blockIdx.y * 128;

    __shared__ __align__(16) float As[16][128];
    __shared__ __align__(16) float Bs[16][128];

    int tid = threadIdx.x;
    int tr = (tid >> 4) * 8;   // row within tile
    int tc = (tid & 15) * 8;   // col within tile

    // loader mapping: thread -> (row = tid/2, kbase = (tid&1)*8), two float4
    int srow = tid >> 1;
    int sk   = (tid & 1) * 8;

    float acc[8][8];
#pragma unroll
    for (int i = 0; i < 8; i++)
#pragma unroll
        for (int j = 0; j < 8; j++) acc[i][j] = 0.f;

    float4 pa0, pa1, pb0, pb1;
    {
        int am = m0 + srow;
        if (am < n) {
            pa0 = *(const float4*)&g_msg[(size_t)am * Hdim + sk];
            pa1 = *(const float4*)&g_msg[(size_t)am * Hdim + sk + 4];
        } else {
            pa0 = make_float4(0, 0, 0, 0); pa1 = pa0;
        }
        pb0 = *(const float4*)&W[(size_t)(n0 + srow) * Hdim + sk];
        pb1 = *(const float4*)&W[(size_t)(n0 + srow) * Hdim + sk + 4];
    }

    for (int k0 = 0; k0 < Hdim; k0 += 16) {
        As[sk + 0][srow] = pa0.x; As[sk + 1][srow] = pa0.y;
        As[sk + 2][srow] = pa0.z; As[sk + 3][srow] = pa0.w;
        As[sk + 4][srow] = pa1.x; As[sk + 5][srow] = pa1.y;
        As[sk + 6][srow] = pa1.z; As[sk + 7][srow] = pa1.w;
        Bs[sk + 0][srow] = pb0.x; Bs[sk + 1][srow] = pb0.y;
        Bs[sk + 2][srow] = pb0.z; Bs[sk + 3][srow] = pb0.w;
        Bs[sk + 4][srow] = pb1.x; Bs[sk + 5][srow] = pb1.y;
        Bs[sk + 6][srow] = pb1.z; Bs[sk + 7][srow] = pb1.w;
        __syncthreads();

        if (k0 + 16 < Hdim) {
            int kn = k0 + 16;
            int am = m0 + srow;
            if (am < n) {
                pa0 = *(const float4*)&g_msg[(size_t)am * Hdim + kn + sk];
                pa1 = *(const float4*)&g_msg[(size_t)am * Hdim + kn + sk + 4];
            } else {
                pa0 = make_float4(0, 0, 0, 0); pa1 = pa0;
            }
            pb0 = *(const float4*)&W[(size_t)(n0 + srow) * Hdim + kn + sk];
            pb1 = *(const float4*)&W[(size_t)(n0 + srow) * Hdim + kn + sk + 4];
        }

#pragma unroll
        for (int kk = 0; kk < 16; kk++) {
            float a[8], b[8];
            *(float4*)&a[0] = *(float4*)&As[kk][tr];
            *(float4*)&a[4] = *(float4*)&As[kk][tr + 4];
            *(float4*)&b[0] = *(float4*)&Bs[kk][tc];
            *(float4*)&b[4] = *(float4*)&Bs[kk][tc + 4];
#pragma unroll
            for (int i = 0; i < 8; i++)
#pragma unroll
                for (int j = 0; j < 8; j++)
                    acc[i][j] = fmaf(a[i], b[j], acc[i][j]);
        }
        __syncthreads();
    }

    float bv[8];
#pragma unroll
    for (int j = 0; j < 8; j++) bv[j] = Bv[n0 + tc + j];

#pragma unroll
    for (int i = 0; i < 8; i++) {
        int m = m0 + tr + i;
        if (m < n) {
            float4 o0, o1;
            o0.x = acc[i][0] + bv[0]; o0.y = acc[i][1] + bv[1];
            o0.z = acc[i][2] + bv[2]; o0.w = acc[i][3] + bv[3];
            o1.x = acc[i][4] + bv[4]; o1.y = acc[i][5] + bv[5];
            o1.z = acc[i][6] + bv[6]; o1.w = acc[i][7] + bv[7];
            *(float4*)&XG[(size_t)m * H3 + n0 + tc]     = o0;
            *(float4*)&XG[(size_t)m * H3 + n0 + tc + 4] = o1;
        }
    }
}

// ---------------- one GRU step: hg = h @ w_hh^T + b_hh; gates; update; scatter ----------------
// grid (16 j-tiles, 4 g-tiles, 2 dirs), 256 threads, tile 64(g) x 64(j) x 3 gates.
__global__ void __launch_bounds__(256) k_step(
    const float* __restrict__ whh_f, const float* __restrict__ bhh_f,
    const float* __restrict__ bih_f,
    const float* __restrict__ whh_b, const float* __restrict__ bhh_b,
    const float* __restrict__ bih_b,
    float* __restrict__ out, int s)
{
    int dir = blockIdx.z;
    const float* W  = dir ? whh_b : whh_f;
    const float* Bh = dir ? bhh_b : bhh_f;
    const float* Bi = dir ? bih_b : bih_f;
    const float* xg = g_xg[dir];
    const float* hin  = g_h[dir][s & 1];
    float*       hout = g_h[dir][(s & 1) ^ 1];
    int t = dir ? (Ldim - 1 - s) : s;

    int j0 = blockIdx.x * 64;
    int g0 = blockIdx.y * 64;

    __shared__ __align__(16) float Hs[16][64];
    __shared__ __align__(16) float Ws[3][16][64];

    int tid = threadIdx.x;
    int tg = tid >> 5;       // 0..7  -> 8 g-rows each
    int tj = tid & 31;       // 0..31 -> 2 j-cols each

    // loader mapping: row = tid/4 (0..63), k4 = (tid&3)*4
    int lrow = tid >> 2;
    int lk = (tid & 3) * 4;

    float accr[8][2], accz[8][2], accn[8][2];
#pragma unroll
    for (int i = 0; i < 8; i++) {
        accr[i][0] = accr[i][1] = 0.f;
        accz[i][0] = accz[i][1] = 0.f;
        accn[i][0] = accn[i][1] = 0.f;
    }

    float4 ph, pw0, pw1, pw2;
    ph  = *(const float4*)&hin[(g0 + lrow) * Hdim + lk];
    pw0 = *(const float4*)&W[(size_t)(0 * Hdim + j0 + lrow) * Hdim + lk];
    pw1 = *(const float4*)&W[(size_t)(1 * Hdim + j0 + lrow) * Hdim + lk];
    pw2 = *(const float4*)&W[(size_t)(2 * Hdim + j0 + lrow) * Hdim + lk];

    for (int k0 = 0; k0 < Hdim; k0 += 16) {
        Hs[lk + 0][lrow] = ph.x;  Hs[lk + 1][lrow] = ph.y;
        Hs[lk + 2][lrow] = ph.z;  Hs[lk + 3][lrow] = ph.w;
        Ws[0][lk + 0][lrow] = pw0.x; Ws[0][lk + 1][lrow] = pw0.y;
        Ws[0][lk + 2][lrow] = pw0.z; Ws[0][lk + 3][lrow] = pw0.w;
        Ws[1][lk + 0][lrow] = pw1.x; Ws[1][lk + 1][lrow] = pw1.y;
        Ws[1][lk + 2][lrow] = pw1.z; Ws[1][lk + 3][lrow] = pw1.w;
        Ws[2][lk + 0][lrow] = pw2.x; Ws[2][lk + 1][lrow] = pw2.y;
        Ws[2][lk + 2][lrow] = pw2.z; Ws[2][lk + 3][lrow] = pw2.w;
        __syncthreads();

        if (k0 + 16 < Hdim) {
            int kn = k0 + 16;
            ph  = *(const float4*)&hin[(g0 + lrow) * Hdim + kn + lk];
            pw0 = *(const float4*)&W[(size_t)(0 * Hdim + j0 + lrow) * Hdim + kn + lk];
            pw1 = *(const float4*)&W[(size_t)(1 * Hdim + j0 + lrow) * Hdim + kn + lk];
            pw2 = *(const float4*)&W[(size_t)(2 * Hdim + j0 + lrow) * Hdim + kn + lk];
        }

#pragma unroll
        for (int kk = 0; kk < 16; kk++) {
            float a[8];
            *(float4*)&a[0] = *(float4*)&Hs[kk][tg * 8];
            *(float4*)&a[4] = *(float4*)&Hs[kk][tg * 8 + 4];
            float2 wr = *(float2*)&Ws[0][kk][tj * 2];
            float2 wz = *(float2*)&Ws[1][kk][tj * 2];
            float2 wn = *(float2*)&Ws[2][kk][tj * 2];
#pragma unroll
            for (int i = 0; i < 8; i++) {
                accr[i][0] = fmaf(a[i], wr.x, accr[i][0]);
                accr[i][1] = fmaf(a[i], wr.y, accr[i][1]);
                accz[i][0] = fmaf(a[i], wz.x, accz[i][0]);
                accz[i][1] = fmaf(a[i], wz.y, accz[i][1]);
                accn[i][0] = fmaf(a[i], wn.x, accn[i][0]);
                accn[i][1] = fmaf(a[i], wn.y, accn[i][1]);
            }
        }
        __syncthreads();
    }

    // epilogue: gates + update + scatter
    int stA[8], cntA[8];
#pragma unroll
    for (int i = 0; i < 8; i++) {
        int g = g0 + tg * 8 + i;
        stA[i] = g_start[g];
        cntA[i] = g_start[g + 1] - stA[i];
    }

#pragma unroll
    for (int p = 0; p < 2; p++) {
        int j = j0 + tj * 2 + p;
        float bhr = Bh[j], bhz = Bh[Hdim + j], bhn = Bh[2 * Hdim + j];
        float bir = Bi[j], biz = Bi[Hdim + j], bin_ = Bi[2 * Hdim + j];
#pragma unroll
        for (int i = 0; i < 8; i++) {
            int g = g0 + tg * 8 + i;
            bool valid = (t < cntA[i]);
            float xr, xz, xn;
            if (valid) {
                size_t base = (size_t)(stA[i] + t) * H3;
                xr = xg[base + j];
                xz = xg[base + Hdim + j];
                xn = xg[base + 2 * Hdim + j];
            } else {
                xr = bir; xz = biz; xn = bin_;
            }
            float r  = 1.f / (1.f + expf(-(xr + accr[i][p] + bhr)));
            float z  = 1.f / (1.f + expf(-(xz + accz[i][p] + bhz)));
            float nn = tanhf(xn + r * (accn[i][p] + bhn));
            float hprev = hin[g * Hdim + j];
            float hnew = (1.f - z) * nn + z * hprev;
            hout[g * Hdim + j] = hnew;
            if (valid)
                out[(size_t)(stA[i] + t) * (2 * Hdim) + dir * Hdim + j] = hnew;
        }
    }
}

// ---------------- host launcher ----------------
extern "C" void kernel_launch(void* const* d_in, const int* in_sizes, int n_in,
                              void* d_out, int out_size)
{
    int nAtoms = in_sizes[0] / Hdim;

    const float* h_atom = (const float*)d_in[0];
    int iBatch, iBias, iWihF, iWhhF, iBihF, iBhhF, iWihB, iWhhB, iBihB, iBhhB;
    if (in_sizes[1] == nAtoms) {
        // setup_inputs dict order: h_atom, batch, bias, w_ih_f, w_hh_f, b_ih_f, b_hh_f, ...
        iBatch = 1; iBias = 2; iWihF = 3; iWhhF = 4; iBihF = 5; iBhhF = 6;
        iWihB = 7; iWhhB = 8; iBihB = 9; iBhhB = 10;
    } else {
        // reference signature order: h_atom, bias, w_ih_f, w_hh_f, b_ih_f, b_hh_f,
        //                            w_ih_b, w_hh_b, b_ih_b, b_hh_b, batch
        iBias = 1; iWihF = 2; iWhhF = 3; iBihF = 4; iBhhF = 5;
        iWihB = 6; iWhhB = 7; iBihB = 8; iBhhB = 9; iBatch = 10;
    }

    const int*   batch = (const int*)d_in[iBatch];
    const float* bias  = (const float*)d_in[iBias];
    const float* wihf  = (const float*)d_in[iWihF];
    const float* whhf  = (const float*)d_in[iWhhF];
    const float* bihf  = (const float*)d_in[iBihF];
    const float* bhhf  = (const float*)d_in[iBhhF];
    const float* wihb  = (const float*)d_in[iWihB];
    const float* whhb  = (const float*)d_in[iWhhB];
    const float* bihb  = (const float*)d_in[iBihB];
    const float* bhhb  = (const float*)d_in[iBhhB];
    float* out = (float*)d_out;

    // 1. segment starts
    k_meta<<<1, 512>>>(batch, nAtoms);

    // 2. message = relu(h_atom + bias)
    int n4 = nAtoms * Hdim / 4;
    k_message<<<(n4 + 255) / 256, 256>>>(h_atom, bias, n4);

    // 3. h0 = segment max
    k_h0<<<Gdim, 256>>>(h_atom);

    // 4. input-gate projections for both dirs
    dim3 gg(H3 / 128, (nAtoms + 127) / 128, 2);
    k_gemm_xg<<<gg, 256>>>(wihf, bihf, wihb, bihb, nAtoms);

    // 5. 128 recurrence steps (both dirs per launch)
    dim3 gs(Hdim / 64, Gdim / 64, 2);
    for (int s = 0; s < Ldim; s++) {
        k_step<<<gs, 256>>>(whhf, bhhf, bihf, whhb, bhhb, bihb, out, s);
    }
}